// round 3
// baseline (speedup 1.0000x reference)
#include <cuda_runtime.h>
#include <cstdint>

// HashGrid encode: 16 levels, F=2, T=2^19, base_res=16, per_level_scale=2.0,
// smoothstep, 2D. Levels 0..5 dense, 6..15 hashed.
//
// v3: revert smem transpose (v2 regression: occupancy collapse + smem wavefronts
//     on the same l1tex pipe). Keep v1 direct stores. Add 2 points/thread for
//     doubled gather MLP, plus L1/L2 cache-policy split.

#define NLEVELS 16
#define LOG2_T 19
#define TSIZE (1u << LOG2_T)
#define PRIME1 2654435761u

__global__ __launch_bounds__(256) void hashgrid_encode_kernel(
    const float4* __restrict__ x2,         // [N/2] = two points per float4
    const float2* __restrict__ table,      // [16 * T] float2 entries
    float* __restrict__ out,               // [N, 32]
    int npairs)
{
    int gi = blockIdx.x * blockDim.x + threadIdx.x;
    if (gi >= npairs) return;

    float4 xp = __ldg(&x2[gi]);
    // map [-1,1] -> [0,1]; point A = (x,y), point B = (z,w)
    float ax = xp.x * 0.5f + 0.5f;
    float ay = xp.y * 0.5f + 0.5f;
    float bx = xp.z * 0.5f + 0.5f;
    float by = xp.w * 0.5f + 0.5f;

    float accA[2 * NLEVELS];
    float accB[2 * NLEVELS];

#pragma unroll
    for (int l = 0; l < NLEVELS; ++l) {
        const unsigned res = 16u << l;                 // power of two
        const float scale = (float)(res - 1u);
        const float2* tl = table + (size_t)l * TSIZE;

        // ---- index computation for both points ----
        float pa0 = ax * scale + 0.5f, pa1 = ay * scale + 0.5f;
        float pb0 = bx * scale + 0.5f, pb1 = by * scale + 0.5f;
        float fa0 = floorf(pa0), fa1 = floorf(pa1);
        float fb0 = floorf(pb0), fb1 = floorf(pb1);
        float ra0 = pa0 - fa0, ra1 = pa1 - fa1;
        float rb0 = pb0 - fb0, rb1 = pb1 - fb1;
        unsigned ga0 = (unsigned)(int)fa0, ga1 = (unsigned)(int)fa1;
        unsigned gb0 = (unsigned)(int)fb0, gb1 = (unsigned)(int)fb1;

        unsigned a00, a10, a01, a11, b00, b10, b01, b11;
        if (l <= 5) {
            const unsigned mask = (res * res) - 1u;
            unsigned abase0 = ga0 + ga1 * res, abase1 = abase0 + res;
            unsigned bbase0 = gb0 + gb1 * res, bbase1 = bbase0 + res;
            a00 = abase0 & mask; a10 = (abase0 + 1u) & mask;
            a01 = abase1 & mask; a11 = (abase1 + 1u) & mask;
            b00 = bbase0 & mask; b10 = (bbase0 + 1u) & mask;
            b01 = bbase1 & mask; b11 = (bbase1 + 1u) & mask;
        } else {
            const unsigned hmask = TSIZE - 1u;
            unsigned hay0 = ga1 * PRIME1, hay1 = hay0 + PRIME1;
            unsigned hby0 = gb1 * PRIME1, hby1 = hby0 + PRIME1;
            a00 = (ga0 ^ hay0) & hmask; a10 = ((ga0 + 1u) ^ hay0) & hmask;
            a01 = (ga0 ^ hay1) & hmask; a11 = ((ga0 + 1u) ^ hay1) & hmask;
            b00 = (gb0 ^ hby0) & hmask; b10 = ((gb0 + 1u) ^ hby0) & hmask;
            b01 = (gb0 ^ hby1) & hmask; b11 = ((gb0 + 1u) ^ hby1) & hmask;
        }

        // ---- 8 gathers issued back-to-back (MLP) ----
        float2 fA00, fA10, fA01, fA11, fB00, fB10, fB01, fB11;
        if (l <= 3) {
            fA00 = __ldg(tl + a00); fA10 = __ldg(tl + a10);
            fA01 = __ldg(tl + a01); fA11 = __ldg(tl + a11);
            fB00 = __ldg(tl + b00); fB10 = __ldg(tl + b10);
            fB01 = __ldg(tl + b01); fB11 = __ldg(tl + b11);
        } else {
            fA00 = __ldcg(tl + a00); fA10 = __ldcg(tl + a10);
            fA01 = __ldcg(tl + a01); fA11 = __ldcg(tl + a11);
            fB00 = __ldcg(tl + b00); fB10 = __ldcg(tl + b10);
            fB01 = __ldcg(tl + b01); fB11 = __ldcg(tl + b11);
        }

        // ---- smoothstep weights + bilinear blend ----
        float wa0 = ra0 * ra0 * (3.0f - 2.0f * ra0);
        float wa1 = ra1 * ra1 * (3.0f - 2.0f * ra1);
        float wb0 = rb0 * rb0 * (3.0f - 2.0f * rb0);
        float wb1 = rb1 * rb1 * (3.0f - 2.0f * rb1);

        float cA00 = (1.0f - wa0) * (1.0f - wa1);
        float cA10 = wa0 * (1.0f - wa1);
        float cA01 = (1.0f - wa0) * wa1;
        float cA11 = wa0 * wa1;
        float cB00 = (1.0f - wb0) * (1.0f - wb1);
        float cB10 = wb0 * (1.0f - wb1);
        float cB01 = (1.0f - wb0) * wb1;
        float cB11 = wb0 * wb1;

        accA[2*l]   = cA00*fA00.x + cA10*fA10.x + cA01*fA01.x + cA11*fA11.x;
        accA[2*l+1] = cA00*fA00.y + cA10*fA10.y + cA01*fA01.y + cA11*fA11.y;
        accB[2*l]   = cB00*fB00.x + cB10*fB10.x + cB01*fB01.x + cB11*fB11.x;
        accB[2*l+1] = cB00*fB00.y + cB10*fB10.y + cB01*fB01.y + cB11*fB11.y;
    }

    // point A: 128 contiguous bytes, then point B
    float4* oa = reinterpret_cast<float4*>(out + (size_t)(2 * gi) * (2 * NLEVELS));
#pragma unroll
    for (int k = 0; k < 8; ++k)
        oa[k] = make_float4(accA[4*k], accA[4*k+1], accA[4*k+2], accA[4*k+3]);
    float4* ob = oa + 8;
#pragma unroll
    for (int k = 0; k < 8; ++k)
        ob[k] = make_float4(accB[4*k], accB[4*k+1], accB[4*k+2], accB[4*k+3]);
}

extern "C" void kernel_launch(void* const* d_in, const int* in_sizes, int n_in,
                              void* d_out, int out_size)
{
    const float4* x     = (const float4*)d_in[0];   // [N,2] f32, viewed as pairs
    const float2* table = (const float2*)d_in[1];   // [16, T, 2] f32
    float* out          = (float*)d_out;            // [N, 32] f32

    int n = in_sizes[0] / 2;        // points (even: 524288)
    int npairs = n / 2;
    int threads = 256;
    int blocks = (npairs + threads - 1) / threads;
    hashgrid_encode_kernel<<<blocks, threads>>>(x, table, out, npairs);
}

// round 4
// speedup vs baseline: 1.2949x; 1.2949x over previous
#include <cuda_runtime.h>
#include <cstdint>

// HashGrid encode: 16 levels, F=2, T=2^19, base_res=16, per_level_scale=2.0,
// smoothstep, 2D. Levels 0..5 dense, 6..15 hashed.
//
// v4 = v1 (best: 106.8us, occ 80.7%) + corner-pair gather merging.
// Key identity: PRIMES=(1,p) => row corners hash to h and h^1 when x is even
// (and idx, idx+1 for dense levels). Those are adjacent 8B entries = one
// aligned float4. For 50% of points each level needs 2 LDG.128 instead of
// 4 LDG.64 -> hashed l1tex wavefronts 40 -> ~30 per point.
// NO smem, NO launch_bounds cap, NO multi-point threads (R2/R3 regressions:
// occupancy is the MLP source here).

#define NLEVELS 16
#define LOG2_T 19
#define TSIZE (1u << LOG2_T)
#define PRIME1 2654435761u

__global__ __launch_bounds__(256) void hashgrid_encode_kernel(
    const float2* __restrict__ x,          // [N] points in [-1,1]
    const float2* __restrict__ table,      // [16 * T] float2 entries
    float* __restrict__ out,               // [N, 32]
    int n)
{
    int i = blockIdx.x * blockDim.x + threadIdx.x;
    if (i >= n) return;

    float2 xi = __ldg(&x[i]);
    float x0 = xi.x * 0.5f + 0.5f;
    float x1 = xi.y * 0.5f + 0.5f;

    float acc[2 * NLEVELS];

#pragma unroll
    for (int l = 0; l < NLEVELS; ++l) {
        const unsigned res = 16u << l;                 // power of two
        const float scale = (float)(res - 1u);

        float p0 = x0 * scale + 0.5f;
        float p1 = x1 * scale + 0.5f;
        float fl0 = floorf(p0);
        float fl1 = floorf(p1);
        float fr0 = p0 - fl0;
        float fr1 = p1 - fl1;
        unsigned g0 = (unsigned)(int)fl0;
        unsigned g1 = (unsigned)(int)fl1;

        // smoothstep weights
        float w0 = fr0 * fr0 * (3.0f - 2.0f * fr0);
        float w1 = fr1 * fr1 * (3.0f - 2.0f * fr1);

        unsigned i00, i10, i01, i11;
        if (l <= 5) {
            const unsigned mask = (res * res) - 1u;
            unsigned b0 = g0 + g1 * res;
            unsigned b1 = b0 + res;
            i00 = b0 & mask;        i10 = (b0 + 1u) & mask;
            i01 = b1 & mask;        i11 = (b1 + 1u) & mask;
        } else {
            const unsigned hmask = TSIZE - 1u;
            unsigned hy0 = g1 * PRIME1;
            unsigned hy1 = hy0 + PRIME1;
            i00 = (g0 ^ hy0) & hmask;        i10 = ((g0 + 1u) ^ hy0) & hmask;
            i01 = (g0 ^ hy1) & hmask;        i11 = ((g0 + 1u) ^ hy1) & hmask;
        }

        const float2* tl = table + (size_t)l * TSIZE;
        float2 f00, f10, f01, f11;

        if ((g0 & 1u) == 0u) {
            // x even: i10 == i00 ^ 1 and i11 == i01 ^ 1 (hashed: x+1 = x^1;
            // dense: i00,i01 even so +1 stays in the pair, no mask wrap).
            // Each row's two corners are one aligned float4.
            const float4* tl4 = reinterpret_cast<const float4*>(tl);
            float4 v0 = __ldg(tl4 + (i00 >> 1));
            float4 v1 = __ldg(tl4 + (i01 >> 1));
            if (i00 & 1u) { f00 = make_float2(v0.z, v0.w); f10 = make_float2(v0.x, v0.y); }
            else          { f00 = make_float2(v0.x, v0.y); f10 = make_float2(v0.z, v0.w); }
            if (i01 & 1u) { f01 = make_float2(v1.z, v1.w); f11 = make_float2(v1.x, v1.y); }
            else          { f01 = make_float2(v1.x, v1.y); f11 = make_float2(v1.z, v1.w); }
        } else {
            f00 = __ldg(tl + i00);
            f10 = __ldg(tl + i10);
            f01 = __ldg(tl + i01);
            f11 = __ldg(tl + i11);
        }

        float c00 = (1.0f - w0) * (1.0f - w1);
        float c10 = w0 * (1.0f - w1);
        float c01 = (1.0f - w0) * w1;
        float c11 = w0 * w1;

        acc[2 * l]     = c00 * f00.x + c10 * f10.x + c01 * f01.x + c11 * f11.x;
        acc[2 * l + 1] = c00 * f00.y + c10 * f10.y + c01 * f01.y + c11 * f11.y;
    }

    float4* o4 = reinterpret_cast<float4*>(out + (size_t)i * (2 * NLEVELS));
#pragma unroll
    for (int k = 0; k < (2 * NLEVELS) / 4; ++k) {
        o4[k] = make_float4(acc[4 * k], acc[4 * k + 1], acc[4 * k + 2], acc[4 * k + 3]);
    }
}

extern "C" void kernel_launch(void* const* d_in, const int* in_sizes, int n_in,
                              void* d_out, int out_size)
{
    const float2* x     = (const float2*)d_in[0];   // [N,2] float32
    const float2* table = (const float2*)d_in[1];   // [16, T, 2] float32
    float* out          = (float*)d_out;            // [N, 32] float32

    int n = in_sizes[0] / 2;
    int threads = 256;
    int blocks = (n + threads - 1) / threads;
    hashgrid_encode_kernel<<<blocks, threads>>>(x, table, out, n);
}